// round 10
// baseline (speedup 1.0000x reference)
#include <cuda_runtime.h>
#include <cuda_bf16.h>
#include <cuda_fp16.h>
#include <cstdint>
#include <math.h>

#define NN 100000
#define F_IN 500
#define HD 128
#define NC 40
#define HD2 256
#define NC2 80
#define EMAX_S 3300000
#define EMAX_K 640000

__device__ float  g_h1[(size_t)NN * HD];     // x @ W1 (fp32, self-loop path)
__device__ __half g_h1h[(size_t)NN * HD];    // fp16 mirror for gather
__device__ float  g_R1[(size_t)NN * HD2];    // relu(concat) FINAL (written by agg1)
__device__ float  g_h2[(size_t)NN * NC];     // R1' @ W2 (fp32)
__device__ __half g_h2h[(size_t)NN * NC];    // fp16 mirror for gather
__device__ float  g_R2[(size_t)NN * NC2];    // layer-2 FINAL (written by agg2)
__device__ float  g_dinv_s[NN];
__device__ float  g_dinv_k[NN];
__device__ int    g_cnt_s[NN], g_cnt_k[NN];
__device__ int    g_rp_s[NN],  g_rp_k[NN];
__device__ int    g_cur_s[NN], g_cur_k[NN];
__device__ int2   g_col_s[EMAX_S];           // {src, bits(dinv[src])}
__device__ int2   g_col_k[EMAX_K];
__device__ int    g_is64;
// W1^T split into bf16 hi/lo, layout [chunk=8][n=128][k=64]
__device__ __nv_bfloat16 g_W1h[8 * 128 * 64];
__device__ __nv_bfloat16 g_W1l[8 * 128 * 64];

// ---------------- dtype detection (int32 vs int64 edge indices) -------------
__global__ void detect_kernel(const void* edges) {
    __shared__ int bad;
    if (threadIdx.x == 0) bad = 0;
    __syncthreads();
    const long long* p = (const long long*)edges;
    for (int i = threadIdx.x; i < 2048; i += blockDim.x) {
        long long v = p[i];
        if (v < 0 || v >= NN) bad = 1;
    }
    __syncthreads();
    if (threadIdx.x == 0) g_is64 = bad ? 0 : 1;
}

__device__ __forceinline__ int edge_at(const void* edges, long long idx, bool is64) {
    return is64 ? (int)((const long long*)edges)[idx] : ((const int*)edges)[idx];
}

// ---------------- CSR build --------------------------------------------------
__global__ void zero_kernel() {
    int i = blockIdx.x * blockDim.x + threadIdx.x;
    if (i < NN) { g_cnt_s[i] = 0; g_cnt_k[i] = 0; }
}

__global__ void count_kernel(const void* edges, int E, int* cnt) {
    int e = blockIdx.x * blockDim.x + threadIdx.x;
    if (e >= E) return;
    bool is64 = g_is64;
    int dst = edge_at(edges, (long long)E + e, is64);
    atomicAdd(&cnt[dst], 1);
}

__device__ void scan_one(const int* cnt, int* rp, int* cur, float* dinv, int* ssum) {
    int t = threadIdx.x;
    const int CH = (NN + 1023) / 1024;
    int start = t * CH, end = min(start + CH, NN);
    int s = 0;
    for (int i = start; i < end; i++) s += cnt[i];
    ssum[t] = s;
    __syncthreads();
    for (int off = 1; off < 1024; off <<= 1) {
        int v = (t >= off) ? ssum[t - off] : 0;
        __syncthreads();
        ssum[t] += v;
        __syncthreads();
    }
    int run = ssum[t] - s;   // exclusive prefix
    for (int i = start; i < end; i++) {
        rp[i] = run; cur[i] = run;
        dinv[i] = rsqrtf((float)(cnt[i] + 1));
        run += cnt[i];
    }
}

__global__ void scan_kernel() {
    __shared__ int ssum[1024];
    scan_one(g_cnt_s, g_rp_s, g_cur_s, g_dinv_s, ssum);
    __syncthreads();
    scan_one(g_cnt_k, g_rp_k, g_cur_k, g_dinv_k, ssum);
}

__global__ void fill_kernel(const void* edges, int E, int* cur, int2* col2,
                            const float* __restrict__ dinv) {
    int e = blockIdx.x * blockDim.x + threadIdx.x;
    if (e >= E) return;
    bool is64 = g_is64;
    int src = edge_at(edges, e, is64);
    int dst = edge_at(edges, (long long)E + e, is64);
    int pos = atomicAdd(&cur[dst], 1);
    col2[pos] = make_int2(src, __float_as_int(__ldg(&dinv[src])));
}

// ---------------- W1 split + transpose: [k][n] -> [chunk][n][k64] -----------
__global__ void w1split_kernel(const float* __restrict__ W1) {
    int i = blockIdx.x * blockDim.x + threadIdx.x;
    if (i >= 512 * 128) return;
    int k = i >> 7, n = i & 127;
    float v = (k < F_IN) ? W1[(size_t)k * HD + n] : 0.f;
    __nv_bfloat16 h = __float2bfloat16_rn(v);
    __nv_bfloat16 l = __float2bfloat16_rn(v - __bfloat162float(h));
    int chunk = k >> 6, kk = k & 63;
    int off = (chunk * 128 + n) * 64 + kk;
    g_W1h[off] = h;
    g_W1l[off] = l;
}

// ---------------- GEMM1: double-buffered cp.async + mma.sync bf16 split -----
__device__ __forceinline__ void mma16816(float* c, const uint32_t* a, const uint32_t* b) {
    asm volatile("mma.sync.aligned.m16n8k16.row.col.f32.bf16.bf16.f32 "
                 "{%0,%1,%2,%3}, {%4,%5,%6,%7}, {%8,%9}, {%0,%1,%2,%3};"
                 : "+f"(c[0]), "+f"(c[1]), "+f"(c[2]), "+f"(c[3])
                 : "r"(a[0]), "r"(a[1]), "r"(a[2]), "r"(a[3]), "r"(b[0]), "r"(b[1]));
}

__device__ __forceinline__ uint32_t smem_u32(const void* p) {
    uint32_t a;
    asm("{ .reg .u64 t; cvta.to.shared.u64 t, %1; cvt.u32.u64 %0, t; }" : "=r"(a) : "l"(p));
    return a;
}
#define CP_ASYNC16(dst32, src) \
    asm volatile("cp.async.cg.shared.global [%0], [%1], 16;" :: "r"(dst32), "l"(src))
#define CP_COMMIT() asm volatile("cp.async.commit_group;" ::: "memory")
#define CP_WAIT0()  asm volatile("cp.async.wait_group 0;" ::: "memory")

#define LDA 72                       // padded row length (bf16/halves)
#define BUFH (128 * LDA)             // halves per A/B array
#define G1_BUF (4 * BUFH)            // halves per buffer (Ah,Al,Bh,Bl)
#define G1_SMEM (2 * G1_BUF * 2)     // bytes: two buffers

__device__ __forceinline__ void g1_load_a(const float* xp, bool rowok, int k0, int akh,
                                          float* areg) {
#pragma unroll
    for (int j = 0; j < 32; j += 4) {
        int gk = k0 + akh + j;
        float4 v = make_float4(0.f, 0.f, 0.f, 0.f);
        if (rowok && gk < F_IN) v = *(const float4*)(xp + gk);
        areg[j] = v.x; areg[j + 1] = v.y; areg[j + 2] = v.z; areg[j + 3] = v.w;
    }
}

__device__ __forceinline__ void g1_store_a(__nv_bfloat16* Ah, __nv_bfloat16* Al,
                                           int ar, int akh, const float* areg) {
#pragma unroll
    for (int j = 0; j < 32; j += 8) {
        __nv_bfloat16 hb[8], lb[8];
#pragma unroll
        for (int q = 0; q < 8; q++) {
            float v = areg[j + q];
            hb[q] = __float2bfloat16_rn(v);
            lb[q] = __float2bfloat16_rn(v - __bfloat162float(hb[q]));
        }
        *(uint4*)&Ah[ar * LDA + akh + j] = *(uint4*)hb;
        *(uint4*)&Al[ar * LDA + akh + j] = *(uint4*)lb;
    }
}

__device__ __forceinline__ void g1_issue_b(int chunk, uint32_t bh32, uint32_t bl32, int tid) {
    const char* sh = (const char*)(g_W1h + chunk * 8192);
    const char* sl = (const char*)(g_W1l + chunk * 8192);
#pragma unroll
    for (int it = 0; it < 4; it++) {
        int idx = tid + it * 256;
        int n = idx >> 3, kg = idx & 7;
        uint32_t doff = (uint32_t)(n * LDA + kg * 8) * 2;
        CP_ASYNC16(bh32 + doff, sh + (size_t)idx * 16);
        CP_ASYNC16(bl32 + doff, sl + (size_t)idx * 16);
    }
}

__global__ void __launch_bounds__(256, 1) gemm1_mma(const float* __restrict__ x) {
    extern __shared__ __nv_bfloat16 smem[];
    uint32_t sb32 = smem_u32(smem);

    int tid = threadIdx.x;
    int lane = tid & 31, wid = tid >> 5;
    int wm = wid & 3, wn = wid >> 2;
    int gr = lane >> 2, tig = lane & 3;
    int row0 = blockIdx.x * 128;

    int ar = tid >> 1;
    int akh = (tid & 1) * 32;
    bool rowok = (row0 + ar) < NN;
    const float* xp = x + (size_t)(row0 + ar) * F_IN;

    float c[2][8][4];
#pragma unroll
    for (int mt = 0; mt < 2; mt++)
#pragma unroll
        for (int nt = 0; nt < 8; nt++)
#pragma unroll
            for (int q = 0; q < 4; q++) c[mt][nt][q] = 0.f;

    float areg[32];

    g1_issue_b(0, sb32 + (2 * BUFH) * 2, sb32 + (3 * BUFH) * 2, tid);
    CP_COMMIT();
    g1_load_a(xp, rowok, 0, akh, areg);
    g1_store_a(smem, smem + BUFH, ar, akh, areg);
    CP_WAIT0();
    __syncthreads();

    for (int chunk = 0; chunk < 8; chunk++) {
        int p = chunk & 1, pn = p ^ 1;
        __nv_bfloat16* Ah = smem + p * G1_BUF;
        __nv_bfloat16* Al = Ah + BUFH;
        __nv_bfloat16* Bh = Al + BUFH;
        __nv_bfloat16* Bl = Bh + BUFH;

        if (chunk < 7) {
            g1_issue_b(chunk + 1, sb32 + (pn * G1_BUF + 2 * BUFH) * 2,
                       sb32 + (pn * G1_BUF + 3 * BUFH) * 2, tid);
            CP_COMMIT();
            g1_load_a(xp, rowok, (chunk + 1) * 64, akh, areg);
        }
#pragma unroll
        for (int ks = 0; ks < 4; ks++) {
            int kk = ks * 16;
            uint32_t ah[2][4], al[2][4], bhf[8][2], blf[8][2];
#pragma unroll
            for (int mt = 0; mt < 2; mt++) {
                int rb = wm * 32 + mt * 16;
                ah[mt][0] = *(uint32_t*)&Ah[(rb + gr) * LDA + kk + tig * 2];
                ah[mt][1] = *(uint32_t*)&Ah[(rb + gr + 8) * LDA + kk + tig * 2];
                ah[mt][2] = *(uint32_t*)&Ah[(rb + gr) * LDA + kk + tig * 2 + 8];
                ah[mt][3] = *(uint32_t*)&Ah[(rb + gr + 8) * LDA + kk + tig * 2 + 8];
                al[mt][0] = *(uint32_t*)&Al[(rb + gr) * LDA + kk + tig * 2];
                al[mt][1] = *(uint32_t*)&Al[(rb + gr + 8) * LDA + kk + tig * 2];
                al[mt][2] = *(uint32_t*)&Al[(rb + gr) * LDA + kk + tig * 2 + 8];
                al[mt][3] = *(uint32_t*)&Al[(rb + gr + 8) * LDA + kk + tig * 2 + 8];
            }
#pragma unroll
            for (int nt = 0; nt < 8; nt++) {
                int nb = wn * 64 + nt * 8 + gr;
                bhf[nt][0] = *(uint32_t*)&Bh[nb * LDA + kk + tig * 2];
                bhf[nt][1] = *(uint32_t*)&Bh[nb * LDA + kk + tig * 2 + 8];
                blf[nt][0] = *(uint32_t*)&Bl[nb * LDA + kk + tig * 2];
                blf[nt][1] = *(uint32_t*)&Bl[nb * LDA + kk + tig * 2 + 8];
            }
#pragma unroll
            for (int mt = 0; mt < 2; mt++)
#pragma unroll
                for (int nt = 0; nt < 8; nt++) {
                    mma16816(c[mt][nt], ah[mt], bhf[nt]);
                    mma16816(c[mt][nt], al[mt], bhf[nt]);
                    mma16816(c[mt][nt], ah[mt], blf[nt]);
                }
        }
        if (chunk < 7) {
            g1_store_a(smem + pn * G1_BUF, smem + pn * G1_BUF + BUFH, ar, akh, areg);
            CP_WAIT0();
        }
        __syncthreads();
    }

#pragma unroll
    for (int mt = 0; mt < 2; mt++) {
        int r0 = row0 + wm * 32 + mt * 16 + gr;
#pragma unroll
        for (int nt = 0; nt < 8; nt++) {
            int cc = wn * 64 + nt * 8 + tig * 2;
            if (r0 < NN) {
                *(float2*)(g_h1 + (size_t)r0 * HD + cc) = make_float2(c[mt][nt][0], c[mt][nt][1]);
                *(__half2*)(g_h1h + (size_t)r0 * HD + cc) = __floats2half2_rn(c[mt][nt][0], c[mt][nt][1]);
            }
            if (r0 + 8 < NN) {
                *(float2*)(g_h1 + (size_t)(r0 + 8) * HD + cc) = make_float2(c[mt][nt][2], c[mt][nt][3]);
                *(__half2*)(g_h1h + (size_t)(r0 + 8) * HD + cc) = __floats2half2_rn(c[mt][nt][2], c[mt][nt][3]);
            }
        }
    }
}

// ---------------- agg layer 1: CSR gather (fp16), warp per node -------------
// lane owns 4 feature cols (8B fp16); edges staged in smem, no shfl chains.
__global__ void __launch_bounds__(256) agg1_kernel(const int* __restrict__ rp,
                                                   const int* __restrict__ cnt,
                                                   const int2* __restrict__ col2,
                                                   const float* __restrict__ dinv,
                                                   const float* __restrict__ b1,
                                                   int half) {
    __shared__ int2 se[8][32];
    int lane = threadIdx.x & 31, warp = threadIdx.x >> 5;
    int node = blockIdx.x * 8 + warp;
    if (node >= NN) return;
    int base = rp[node], deg = cnt[node];
    float a0 = 0.f, a1 = 0.f, a2 = 0.f, a3 = 0.f;

    for (int j0 = 0; j0 < deg; j0 += 32) {
        int nb = min(32, deg - j0);
        if (lane < nb) se[warp][lane] = col2[base + j0 + lane];
        __syncwarp();
        if (nb == 32) {
#pragma unroll
            for (int j = 0; j < 32; j++) {
                int2 e = se[warp][j];
                float s = __int_as_float(e.y);
                uint2 hv = *(const uint2*)(g_h1h + (size_t)e.x * HD + lane * 4);
                float2 f0 = __half22float2(*(__half2*)&hv.x);
                float2 f1 = __half22float2(*(__half2*)&hv.y);
                a0 = fmaf(s, f0.x, a0); a1 = fmaf(s, f0.y, a1);
                a2 = fmaf(s, f1.x, a2); a3 = fmaf(s, f1.y, a3);
            }
        } else {
            for (int j = 0; j < nb; j++) {
                int2 e = se[warp][j];
                float s = __int_as_float(e.y);
                uint2 hv = *(const uint2*)(g_h1h + (size_t)e.x * HD + lane * 4);
                float2 f0 = __half22float2(*(__half2*)&hv.x);
                float2 f1 = __half22float2(*(__half2*)&hv.y);
                a0 = fmaf(s, f0.x, a0); a1 = fmaf(s, f0.y, a1);
                a2 = fmaf(s, f1.x, a2); a3 = fmaf(s, f1.y, a3);
            }
        }
        __syncwarp();
    }
    float ds = dinv[node], ds2 = ds * ds;
    float4 h  = *(const float4*)(g_h1 + (size_t)node * HD + lane * 4);
    float4 bb = *(const float4*)(b1 + lane * 4);
    float4 o;
    o.x = fmaxf(fmaf(a0, ds, fmaf(h.x, ds2, bb.x)), 0.f);
    o.y = fmaxf(fmaf(a1, ds, fmaf(h.y, ds2, bb.y)), 0.f);
    o.z = fmaxf(fmaf(a2, ds, fmaf(h.z, ds2, bb.z)), 0.f);
    o.w = fmaxf(fmaf(a3, ds, fmaf(h.w, ds2, bb.w)), 0.f);
    *(float4*)(g_R1 + (size_t)node * HD2 + half * HD + lane * 4) = o;
}

// ---------------- GEMM2: R1'[N,256] @ W2[256,40] -> g_h2 (+fp16 mirror) -----
__global__ void __launch_bounds__(256) gemm2_kernel(const float* __restrict__ W2) {
    __shared__ float As[64][128];
    __shared__ float Bs[64][NC];
    int row0 = blockIdx.x * 128;
    int tid = threadIdx.x;
    int tx = tid & 7;
    int ty = tid >> 3;
    float acc[4][5] = {};
    int ar = tid >> 1;
    int ac0 = (tid & 1) * 32;
    int br = tid >> 2;
    int bc0 = (tid & 3) * 10;

    for (int k0 = 0; k0 < HD2; k0 += 64) {
        int grow = row0 + ar;
#pragma unroll
        for (int j = 0; j < 32; j += 4) {
            float4 v = make_float4(0.f, 0.f, 0.f, 0.f);
            if (grow < NN)
                v = *(const float4*)(g_R1 + (size_t)grow * HD2 + k0 + ac0 + j);
            int cidx = ac0 + j;
            As[cidx + 0][ar] = v.x; As[cidx + 1][ar] = v.y;
            As[cidx + 2][ar] = v.z; As[cidx + 3][ar] = v.w;
        }
#pragma unroll
        for (int j = 0; j < 10; j++)
            Bs[br][bc0 + j] = W2[(size_t)(k0 + br) * NC + bc0 + j];
        __syncthreads();
#pragma unroll 16
        for (int kk = 0; kk < 64; kk++) {
            float a[4], b[5];
            *(float4*)a = *(float4*)&As[kk][ty * 4];
#pragma unroll
            for (int j = 0; j < 5; j++) b[j] = Bs[kk][tx * 5 + j];
#pragma unroll
            for (int i = 0; i < 4; i++)
#pragma unroll
                for (int j = 0; j < 5; j++)
                    acc[i][j] += a[i] * b[j];
        }
        __syncthreads();
    }
#pragma unroll
    for (int i = 0; i < 4; i++) {
        int r = row0 + ty * 4 + i;
        if (r < NN) {
#pragma unroll
            for (int j = 0; j < 5; j++) {
                g_h2[(size_t)r * NC + tx * 5 + j] = acc[i][j];
                g_h2h[(size_t)r * NC + tx * 5 + j] = __float2half_rn(acc[i][j]);
            }
        }
    }
}

// ---------------- agg layer 2: CSR gather (fp16), warp per node -------------
// lanes 0..19 own 2 cols each (4B fp16)
__global__ void __launch_bounds__(256) agg2_kernel(const int* __restrict__ rp,
                                                   const int* __restrict__ cnt,
                                                   const int2* __restrict__ col2,
                                                   const float* __restrict__ dinv,
                                                   const float* __restrict__ b2,
                                                   int half) {
    __shared__ int2 se[8][32];
    int lane = threadIdx.x & 31, warp = threadIdx.x >> 5;
    int node = blockIdx.x * 8 + warp;
    if (node >= NN) return;
    int base = rp[node], deg = cnt[node];
    float a0 = 0.f, a1 = 0.f;
    bool active = lane < 20;

    for (int j0 = 0; j0 < deg; j0 += 32) {
        int nb = min(32, deg - j0);
        if (lane < nb) se[warp][lane] = col2[base + j0 + lane];
        __syncwarp();
        if (nb == 32) {
#pragma unroll
            for (int j = 0; j < 32; j++) {
                int2 e = se[warp][j];
                float s = __int_as_float(e.y);
                if (active) {
                    uint hv = *(const uint*)(g_h2h + (size_t)e.x * NC + lane * 2);
                    float2 f0 = __half22float2(*(__half2*)&hv);
                    a0 = fmaf(s, f0.x, a0); a1 = fmaf(s, f0.y, a1);
                }
            }
        } else {
            for (int j = 0; j < nb; j++) {
                int2 e = se[warp][j];
                float s = __int_as_float(e.y);
                if (active) {
                    uint hv = *(const uint*)(g_h2h + (size_t)e.x * NC + lane * 2);
                    float2 f0 = __half22float2(*(__half2*)&hv);
                    a0 = fmaf(s, f0.x, a0); a1 = fmaf(s, f0.y, a1);
                }
            }
        }
        __syncwarp();
    }
    if (active) {
        float ds = dinv[node], ds2 = ds * ds;
        float2 h = *(const float2*)(g_h2 + (size_t)node * NC + lane * 2);
        float2 bb = *(const float2*)(b2 + lane * 2);
        float2 o;
        o.x = fmaf(a0, ds, fmaf(h.x, ds2, bb.x));
        o.y = fmaf(a1, ds, fmaf(h.y, ds2, bb.y));
        *(float2*)(g_R2 + (size_t)node * NC2 + half * NC + lane * 2) = o;
    }
}

// ---------------- final: Wlin + log_softmax ---------------------------------
__global__ void __launch_bounds__(256) final_kernel(const float* __restrict__ Wlin,
                                                    const float* __restrict__ blin,
                                                    float* __restrict__ out) {
    __shared__ float sWT[NC2 * NC];   // sWT[j*NC + c] = Wlin[c*NC2 + j]
    __shared__ float sblin[NC];
    __shared__ float sr2[8][NC2];
    int tid = threadIdx.x;
    for (int i = tid; i < NC * NC2; i += 256) {
        int cidx = i / NC2, j = i % NC2;
        sWT[j * NC + cidx] = Wlin[i];
    }
    if (tid < NC) sblin[tid] = blin[tid];
    __syncthreads();
    int warp = tid >> 5, lane = tid & 31;
    int node = blockIdx.x * 8 + warp;
    if (node >= NN) return;

    for (int j = lane; j < NC2; j += 32)
        sr2[warp][j] = g_R2[(size_t)node * NC2 + j];
    __syncwarp();

    float l1, l2 = -INFINITY;
    {
        float a = sblin[lane];
#pragma unroll 8
        for (int j = 0; j < NC2; j++) a = fmaf(sr2[warp][j], sWT[j * NC + lane], a);
        l1 = a;
    }
    if (lane < 8) {
        int cidx = 32 + lane;
        float a = sblin[cidx];
#pragma unroll 8
        for (int j = 0; j < NC2; j++) a = fmaf(sr2[warp][j], sWT[j * NC + cidx], a);
        l2 = a;
    }
    float m = fmaxf(l1, l2);
#pragma unroll
    for (int off = 16; off > 0; off >>= 1)
        m = fmaxf(m, __shfl_xor_sync(0xffffffffu, m, off));
    float s = expf(l1 - m) + ((lane < 8) ? expf(l2 - m) : 0.f);
#pragma unroll
    for (int off = 16; off > 0; off >>= 1)
        s += __shfl_xor_sync(0xffffffffu, s, off);
    float lse = logf(s);
    out[(size_t)node * NC + lane] = l1 - m - lse;
    if (lane < 8) out[(size_t)node * NC + 32 + lane] = l2 - m - lse;
}

// ---------------------------------------------------------------------------
extern "C" void kernel_launch(void* const* d_in, const int* in_sizes, int n_in,
                              void* d_out, int out_size) {
    const float* x    = (const float*)d_in[0];
    const void*  es   = d_in[1];
    const void*  ek   = d_in[2];
    const float* W1   = (const float*)d_in[3];
    const float* b1   = (const float*)d_in[4];
    const float* W2   = (const float*)d_in[5];
    const float* b2   = (const float*)d_in[6];
    const float* Wlin = (const float*)d_in[7];
    const float* blin = (const float*)d_in[8];
    float* out = (float*)d_out;

    int E  = in_sizes[1] / 2;
    int Ek = in_sizes[2] / 2;

    int *cnt_s, *cnt_k, *rp_s, *rp_k, *cur_s, *cur_k;
    int2 *col_s, *col_k;
    float *dinv_s, *dinv_k;
    cudaGetSymbolAddress((void**)&cnt_s, g_cnt_s);
    cudaGetSymbolAddress((void**)&cnt_k, g_cnt_k);
    cudaGetSymbolAddress((void**)&rp_s,  g_rp_s);
    cudaGetSymbolAddress((void**)&rp_k,  g_rp_k);
    cudaGetSymbolAddress((void**)&cur_s, g_cur_s);
    cudaGetSymbolAddress((void**)&cur_k, g_cur_k);
    cudaGetSymbolAddress((void**)&col_s, g_col_s);
    cudaGetSymbolAddress((void**)&col_k, g_col_k);
    cudaGetSymbolAddress((void**)&dinv_s, g_dinv_s);
    cudaGetSymbolAddress((void**)&dinv_k, g_dinv_k);

    static int smem_set = 0;
    if (!smem_set) {
        cudaFuncSetAttribute(gemm1_mma, cudaFuncAttributeMaxDynamicSharedMemorySize, G1_SMEM);
        smem_set = 1;
    }

    // slot 3 (profiled) = gemm1_mma
    detect_kernel<<<1, 256>>>(es);
    w1split_kernel<<<(512 * 128 + 255) / 256, 256>>>(W1);
    zero_kernel<<<(NN + 255) / 256, 256>>>();
    gemm1_mma<<<(NN + 127) / 128, 256, G1_SMEM>>>(x);

    count_kernel<<<(E + 255) / 256, 256>>>(es, E, cnt_s);
    count_kernel<<<(Ek + 255) / 256, 256>>>(ek, Ek, cnt_k);
    scan_kernel<<<1, 1024>>>();
    fill_kernel<<<(E + 255) / 256, 256>>>(es, E, cur_s, col_s, dinv_s);
    fill_kernel<<<(Ek + 255) / 256, 256>>>(ek, Ek, cur_k, col_k, dinv_k);

    agg1_kernel<<<(NN + 7) / 8, 256>>>(rp_s, cnt_s, col_s, dinv_s, b1, 0);
    agg1_kernel<<<(NN + 7) / 8, 256>>>(rp_k, cnt_k, col_k, dinv_k, b1, 1);

    gemm2_kernel<<<(NN + 127) / 128, 256>>>(W2);

    agg2_kernel<<<(NN + 7) / 8, 256>>>(rp_s, cnt_s, col_s, dinv_s, b2, 0);
    agg2_kernel<<<(NN + 7) / 8, 256>>>(rp_k, cnt_k, col_k, dinv_k, b2, 1);

    final_kernel<<<(NN + 7) / 8, 256>>>(Wlin, blin, out);
}

// round 11
// speedup vs baseline: 1.1080x; 1.1080x over previous
#include <cuda_runtime.h>
#include <cuda_bf16.h>
#include <cuda_fp16.h>
#include <cstdint>
#include <math.h>

#define NN 100000
#define F_IN 500
#define HD 128
#define NC 40
#define HD2 256
#define NC2 80

__device__ float  g_h1[(size_t)NN * HD];     // x @ W1 (fp32, self-loop path)
__device__ __half g_h1h[(size_t)NN * HD];    // fp16 mirror for scatter gather
__device__ float  g_R1[(size_t)NN * HD2];    // layer-1 atomic accumulator
__device__ float  g_h2[(size_t)NN * NC];     // R1' @ W2 (fp32)
__device__ __half g_h2h[(size_t)NN * NC];    // fp16 mirror for scatter gather
__device__ float  g_R2[(size_t)NN * NC2];    // layer-2 atomic accumulator
__device__ float  g_dinv_s[NN];
__device__ float  g_dinv_k[NN];
__device__ int    g_is64;
// W1^T split into bf16 hi/lo, layout [chunk=8][n=128][k=64]
__device__ __nv_bfloat16 g_W1h[8 * 128 * 64];
__device__ __nv_bfloat16 g_W1l[8 * 128 * 64];

// ---------------- dtype detection (int32 vs int64 edge indices) -------------
__global__ void detect_kernel(const void* edges) {
    __shared__ int bad;
    if (threadIdx.x == 0) bad = 0;
    __syncthreads();
    const long long* p = (const long long*)edges;
    for (int i = threadIdx.x; i < 2048; i += blockDim.x) {
        long long v = p[i];
        if (v < 0 || v >= NN) bad = 1;
    }
    __syncthreads();
    if (threadIdx.x == 0) g_is64 = bad ? 0 : 1;
}

__device__ __forceinline__ int edge_at(const void* edges, long long idx, bool is64) {
    return is64 ? (int)((const long long*)edges)[idx] : ((const int*)edges)[idx];
}

// ---------------- init accumulators + degree seeds --------------------------
__global__ void init_kernel() {
    int i = blockIdx.x * blockDim.x + threadIdx.x;
    float4 z = make_float4(0.f, 0.f, 0.f, 0.f);
    float4 one = make_float4(1.f, 1.f, 1.f, 1.f);
    if (i < NN * (HD2 / 4)) ((float4*)g_R1)[i] = z;
    if (i < NN * (NC2 / 4)) ((float4*)g_R2)[i] = z;
    if (i < NN / 4) { ((float4*)g_dinv_s)[i] = one; ((float4*)g_dinv_k)[i] = one; }
}

__global__ void deg_kernel(const void* edges, int E, float* deg) {
    int e = blockIdx.x * blockDim.x + threadIdx.x;
    if (e >= E) return;
    bool is64 = g_is64;
    int dst = edge_at(edges, (long long)E + e, is64);
    atomicAdd(&deg[dst], 1.0f);
}

__global__ void dinv_kernel() {
    int i = blockIdx.x * blockDim.x + threadIdx.x;
    if (i < NN) {
        g_dinv_s[i] = rsqrtf(g_dinv_s[i]);
        g_dinv_k[i] = rsqrtf(g_dinv_k[i]);
    }
}

// ---------------- W1 split + transpose: [k][n] -> [chunk][n][k64] -----------
__global__ void w1split_kernel(const float* __restrict__ W1) {
    int i = blockIdx.x * blockDim.x + threadIdx.x;
    if (i >= 512 * 128) return;
    int k = i >> 7, n = i & 127;
    float v = (k < F_IN) ? W1[(size_t)k * HD + n] : 0.f;
    __nv_bfloat16 h = __float2bfloat16_rn(v);
    __nv_bfloat16 l = __float2bfloat16_rn(v - __bfloat162float(h));
    int chunk = k >> 6, kk = k & 63;
    int off = (chunk * 128 + n) * 64 + kk;
    g_W1h[off] = h;
    g_W1l[off] = l;
}

// ---------------- GEMM1: single-buffered HMMA, 2 CTAs/SM for overlap --------
__device__ __forceinline__ void mma16816(float* c, const uint32_t* a, const uint32_t* b) {
    asm volatile("mma.sync.aligned.m16n8k16.row.col.f32.bf16.bf16.f32 "
                 "{%0,%1,%2,%3}, {%4,%5,%6,%7}, {%8,%9}, {%0,%1,%2,%3};"
                 : "+f"(c[0]), "+f"(c[1]), "+f"(c[2]), "+f"(c[3])
                 : "r"(a[0]), "r"(a[1]), "r"(a[2]), "r"(a[3]), "r"(b[0]), "r"(b[1]));
}

#define LDA 72   // padded row length (bf16) for conflict-free b32 smem loads
#define G1_SMEM (4 * 128 * LDA * 2)

__global__ void __launch_bounds__(256, 2) gemm1_mma(const float* __restrict__ x) {
    extern __shared__ __nv_bfloat16 smem[];
    __nv_bfloat16* Ah = smem;                 // [128][LDA]
    __nv_bfloat16* Al = Ah + 128 * LDA;
    __nv_bfloat16* Bh = Al + 128 * LDA;       // [128 n][LDA]
    __nv_bfloat16* Bl = Bh + 128 * LDA;

    int tid = threadIdx.x;
    int lane = tid & 31, wid = tid >> 5;
    int wm = wid & 3, wn = wid >> 2;
    int gr = lane >> 2, tig = lane & 3;
    int row0 = blockIdx.x * 128;

    int ar = tid >> 1;
    int akh = (tid & 1) * 32;
    bool rowok = (row0 + ar) < NN;
    const float* xp = x + (size_t)(row0 + ar) * F_IN;

    float c[2][8][4];
#pragma unroll
    for (int mt = 0; mt < 2; mt++)
#pragma unroll
        for (int nt = 0; nt < 8; nt++)
#pragma unroll
            for (int q = 0; q < 4; q++) c[mt][nt][q] = 0.f;

    for (int chunk = 0; chunk < 8; chunk++) {
        int k0 = chunk * 64;
        // ---- load A: fp32 -> split bf16 hi/lo into smem ----
#pragma unroll
        for (int j = 0; j < 32; j += 8) {
            int kk = akh + j, gk = k0 + kk;
            float4 a = make_float4(0.f, 0.f, 0.f, 0.f);
            float4 b = make_float4(0.f, 0.f, 0.f, 0.f);
            if (rowok && gk < F_IN)     a = *(const float4*)(xp + gk);
            if (rowok && gk + 4 < F_IN) b = *(const float4*)(xp + gk + 4);
            float v[8] = {a.x, a.y, a.z, a.w, b.x, b.y, b.z, b.w};
            __nv_bfloat16 hb[8], lb[8];
#pragma unroll
            for (int q = 0; q < 8; q++) {
                hb[q] = __float2bfloat16_rn(v[q]);
                lb[q] = __float2bfloat16_rn(v[q] - __bfloat162float(hb[q]));
            }
            *(uint4*)&Ah[ar * LDA + kk] = *(uint4*)hb;
            *(uint4*)&Al[ar * LDA + kk] = *(uint4*)lb;
        }
        // ---- load B: copy pre-split W1^T [n][k64] ----
        {
            const uint4* sh = (const uint4*)(g_W1h + chunk * 128 * 64);
            const uint4* sl = (const uint4*)(g_W1l + chunk * 128 * 64);
#pragma unroll
            for (int it = 0; it < 4; it++) {
                int idx = tid + it * 256;
                int n = idx >> 3, kg = idx & 7;
                *(uint4*)&Bh[n * LDA + kg * 8] = sh[idx];
                *(uint4*)&Bl[n * LDA + kg * 8] = sl[idx];
            }
        }
        __syncthreads();
#pragma unroll
        for (int ks = 0; ks < 4; ks++) {
            int kk = ks * 16;
            uint32_t ah[2][4], al[2][4], bhf[8][2], blf[8][2];
#pragma unroll
            for (int mt = 0; mt < 2; mt++) {
                int rb = wm * 32 + mt * 16;
                ah[mt][0] = *(uint32_t*)&Ah[(rb + gr) * LDA + kk + tig * 2];
                ah[mt][1] = *(uint32_t*)&Ah[(rb + gr + 8) * LDA + kk + tig * 2];
                ah[mt][2] = *(uint32_t*)&Ah[(rb + gr) * LDA + kk + tig * 2 + 8];
                ah[mt][3] = *(uint32_t*)&Ah[(rb + gr + 8) * LDA + kk + tig * 2 + 8];
                al[mt][0] = *(uint32_t*)&Al[(rb + gr) * LDA + kk + tig * 2];
                al[mt][1] = *(uint32_t*)&Al[(rb + gr + 8) * LDA + kk + tig * 2];
                al[mt][2] = *(uint32_t*)&Al[(rb + gr) * LDA + kk + tig * 2 + 8];
                al[mt][3] = *(uint32_t*)&Al[(rb + gr + 8) * LDA + kk + tig * 2 + 8];
            }
#pragma unroll
            for (int nt = 0; nt < 8; nt++) {
                int nb = wn * 64 + nt * 8 + gr;
                bhf[nt][0] = *(uint32_t*)&Bh[nb * LDA + kk + tig * 2];
                bhf[nt][1] = *(uint32_t*)&Bh[nb * LDA + kk + tig * 2 + 8];
                blf[nt][0] = *(uint32_t*)&Bl[nb * LDA + kk + tig * 2];
                blf[nt][1] = *(uint32_t*)&Bl[nb * LDA + kk + tig * 2 + 8];
            }
#pragma unroll
            for (int mt = 0; mt < 2; mt++)
#pragma unroll
                for (int nt = 0; nt < 8; nt++) {
                    mma16816(c[mt][nt], ah[mt], bhf[nt]);
                    mma16816(c[mt][nt], al[mt], bhf[nt]);
                    mma16816(c[mt][nt], ah[mt], blf[nt]);
                }
        }
        __syncthreads();
    }
    // ---- epilogue: fp32 + fp16 mirror ----
#pragma unroll
    for (int mt = 0; mt < 2; mt++) {
        int r0 = row0 + wm * 32 + mt * 16 + gr;
#pragma unroll
        for (int nt = 0; nt < 8; nt++) {
            int cc = wn * 64 + nt * 8 + tig * 2;
            if (r0 < NN) {
                *(float2*)(g_h1 + (size_t)r0 * HD + cc) = make_float2(c[mt][nt][0], c[mt][nt][1]);
                *(__half2*)(g_h1h + (size_t)r0 * HD + cc) = __floats2half2_rn(c[mt][nt][0], c[mt][nt][1]);
            }
            if (r0 + 8 < NN) {
                *(float2*)(g_h1 + (size_t)(r0 + 8) * HD + cc) = make_float2(c[mt][nt][2], c[mt][nt][3]);
                *(__half2*)(g_h1h + (size_t)(r0 + 8) * HD + cc) = __floats2half2_rn(c[mt][nt][2], c[mt][nt][3]);
            }
        }
    }
}

// -------- scatter 64 cols per pass, fp16 gather: 2 edges/warp, 16 lanes -----
__global__ void scatter64_kernel(const void* edges, int E,
                                 const float* __restrict__ dinv,
                                 int base, int colbase) {
    int t = blockIdx.x * blockDim.x + threadIdx.x;
    int e = t >> 4;
    int l16 = t & 15;
    if (e >= E) return;
    bool is64 = g_is64;
    int src = edge_at(edges, e, is64);
    int dst = edge_at(edges, (long long)E + e, is64);
    float s = __ldg(&dinv[src]);
    const __half2* hp = (const __half2*)(g_h1h + (size_t)src * HD + colbase + l16 * 4);
    float2 f0 = __half22float2(hp[0]);
    float2 f1 = __half22float2(hp[1]);
    float* p = g_R1 + (size_t)dst * HD2 + base + colbase + l16 * 4;
    asm volatile("red.global.add.v4.f32 [%0], {%1,%2,%3,%4};"
                 :: "l"(p), "f"(f0.x * s), "f"(f0.y * s), "f"(f1.x * s), "f"(f1.y * s)
                 : "memory");
}

// ---------------- GEMM2 (fused finalize1 on A-load): R1'[N,256]@W2 -> g_h2 --
__global__ void __launch_bounds__(256) gemm2_kernel(const float* __restrict__ W2,
                                                    const float* __restrict__ b1) {
    __shared__ float As[64][128];
    __shared__ float Bs[64][NC];
    __shared__ float sb1[HD];
    int row0 = blockIdx.x * 128;
    int tid = threadIdx.x;
    int tx = tid & 7;
    int ty = tid >> 3;
    float acc[4][5] = {};
    int ar = tid >> 1;
    int ac0 = (tid & 1) * 32;
    int br = tid >> 2;
    int bc0 = (tid & 3) * 10;

    if (tid < HD) sb1[tid] = b1[tid];
    int grow = row0 + ar;
    bool rowok = grow < NN;
    float dsv = 0.f, dkv = 0.f;
    if (rowok) { dsv = g_dinv_s[grow]; dkv = g_dinv_k[grow]; }
    __syncthreads();

    for (int k0 = 0; k0 < HD2; k0 += 64) {
        float dv = (k0 >= HD) ? dkv : dsv;
        float dv2 = dv * dv;
#pragma unroll
        for (int j = 0; j < 32; j += 4) {
            int cidx = ac0 + j;
            int c = k0 + cidx;
            int cm = c & (HD - 1);
            float4 v = make_float4(0.f, 0.f, 0.f, 0.f);
            float4 h = make_float4(0.f, 0.f, 0.f, 0.f);
            if (rowok) {
                v = *(const float4*)(g_R1 + (size_t)grow * HD2 + c);
                h = *(const float4*)(g_h1 + (size_t)grow * HD + cm);
            }
            float4 bb = *(const float4*)&sb1[cm];
            float4 o;
            o.x = fmaxf(fmaf(v.x, dv, fmaf(h.x, dv2, bb.x)), 0.f);
            o.y = fmaxf(fmaf(v.y, dv, fmaf(h.y, dv2, bb.y)), 0.f);
            o.z = fmaxf(fmaf(v.z, dv, fmaf(h.z, dv2, bb.z)), 0.f);
            o.w = fmaxf(fmaf(v.w, dv, fmaf(h.w, dv2, bb.w)), 0.f);
            As[cidx + 0][ar] = o.x; As[cidx + 1][ar] = o.y;
            As[cidx + 2][ar] = o.z; As[cidx + 3][ar] = o.w;
        }
#pragma unroll
        for (int j = 0; j < 10; j++)
            Bs[br][bc0 + j] = W2[(size_t)(k0 + br) * NC + bc0 + j];
        __syncthreads();
#pragma unroll 16
        for (int kk = 0; kk < 64; kk++) {
            float a[4], b[5];
            *(float4*)a = *(float4*)&As[kk][ty * 4];
#pragma unroll
            for (int j = 0; j < 5; j++) b[j] = Bs[kk][tx * 5 + j];
#pragma unroll
            for (int i = 0; i < 4; i++)
#pragma unroll
                for (int j = 0; j < 5; j++)
                    acc[i][j] += a[i] * b[j];
        }
        __syncthreads();
    }
#pragma unroll
    for (int i = 0; i < 4; i++) {
        int r = row0 + ty * 4 + i;
        if (r < NN) {
#pragma unroll
            for (int j = 0; j < 5; j++) {
                g_h2[(size_t)r * NC + tx * 5 + j] = acc[i][j];
                g_h2h[(size_t)r * NC + tx * 5 + j] = __float2half_rn(acc[i][j]);
            }
        }
    }
}

// ---------------- scatter 40-wide fp16 gather: 10 threads per edge ----------
__global__ void scatter40_kernel(const void* edges, int E,
                                 const float* __restrict__ dinv, int base) {
    long long t = (long long)blockIdx.x * blockDim.x + threadIdx.x;
    if (t >= (long long)E * 10) return;
    int e = (int)(t / 10), j = (int)(t % 10);
    bool is64 = g_is64;
    int src = edge_at(edges, e, is64);
    int dst = edge_at(edges, (long long)E + e, is64);
    float s = __ldg(&dinv[src]);
    const __half2* hp = (const __half2*)(g_h2h + (size_t)src * NC + j * 4);
    float2 f0 = __half22float2(hp[0]);
    float2 f1 = __half22float2(hp[1]);
    float* p = g_R2 + (size_t)dst * NC2 + base + j * 4;
    asm volatile("red.global.add.v4.f32 [%0], {%1,%2,%3,%4};"
                 :: "l"(p), "f"(f0.x * s), "f"(f0.y * s), "f"(f1.x * s), "f"(f1.y * s)
                 : "memory");
}

// ---------------- final: finalize L2 + Wlin + log_softmax -------------------
__global__ void __launch_bounds__(256) final_kernel(const float* __restrict__ b2,
                                                    const float* __restrict__ Wlin,
                                                    const float* __restrict__ blin,
                                                    float* __restrict__ out) {
    __shared__ float sWT[NC2 * NC];   // sWT[j*NC + c] = Wlin[c*NC2 + j]
    __shared__ float sb2[NC], sblin[NC];
    __shared__ float sr2[8][NC2];
    int tid = threadIdx.x;
    for (int i = tid; i < NC * NC2; i += 256) {
        int cidx = i / NC2, j = i % NC2;
        sWT[j * NC + cidx] = Wlin[i];
    }
    if (tid < NC) { sb2[tid] = b2[tid]; sblin[tid] = blin[tid]; }
    __syncthreads();
    int warp = tid >> 5, lane = tid & 31;
    int node = blockIdx.x * 8 + warp;
    if (node >= NN) return;

    float ds = g_dinv_s[node], dk = g_dinv_k[node];
    float ds2 = ds * ds, dk2 = dk * dk;
    for (int j = lane; j < NC; j += 32) {
        float h = g_h2[(size_t)node * NC + j];
        sr2[warp][j]      = fmaf(g_R2[(size_t)node * NC2 + j],      ds, fmaf(h, ds2, sb2[j]));
        sr2[warp][NC + j] = fmaf(g_R2[(size_t)node * NC2 + NC + j], dk, fmaf(h, dk2, sb2[j]));
    }
    __syncwarp();

    float l1, l2 = -INFINITY;
    {
        float a = sblin[lane];
#pragma unroll 8
        for (int j = 0; j < NC2; j++) a = fmaf(sr2[warp][j], sWT[j * NC + lane], a);
        l1 = a;
    }
    if (lane < 8) {
        int cidx = 32 + lane;
        float a = sblin[cidx];
#pragma unroll 8
        for (int j = 0; j < NC2; j++) a = fmaf(sr2[warp][j], sWT[j * NC + cidx], a);
        l2 = a;
    }
    float m = fmaxf(l1, l2);
#pragma unroll
    for (int off = 16; off > 0; off >>= 1)
        m = fmaxf(m, __shfl_xor_sync(0xffffffffu, m, off));
    float s = expf(l1 - m) + ((lane < 8) ? expf(l2 - m) : 0.f);
#pragma unroll
    for (int off = 16; off > 0; off >>= 1)
        s += __shfl_xor_sync(0xffffffffu, s, off);
    float lse = logf(s);
    out[(size_t)node * NC + lane] = l1 - m - lse;
    if (lane < 8) out[(size_t)node * NC + 32 + lane] = l2 - m - lse;
}

// ---------------------------------------------------------------------------
extern "C" void kernel_launch(void* const* d_in, const int* in_sizes, int n_in,
                              void* d_out, int out_size) {
    const float* x    = (const float*)d_in[0];
    const void*  es   = d_in[1];
    const void*  ek   = d_in[2];
    const float* W1   = (const float*)d_in[3];
    const float* b1   = (const float*)d_in[4];
    const float* W2   = (const float*)d_in[5];
    const float* b2   = (const float*)d_in[6];
    const float* Wlin = (const float*)d_in[7];
    const float* blin = (const float*)d_in[8];
    float* out = (float*)d_out;

    int E  = in_sizes[1] / 2;
    int Ek = in_sizes[2] / 2;

    float *dinv_s, *dinv_k;
    cudaGetSymbolAddress((void**)&dinv_s, g_dinv_s);
    cudaGetSymbolAddress((void**)&dinv_k, g_dinv_k);

    static int smem_set = 0;
    if (!smem_set) {
        cudaFuncSetAttribute(gemm1_mma, cudaFuncAttributeMaxDynamicSharedMemorySize, G1_SMEM);
        smem_set = 1;
    }

    // launch #4 = gemm1_mma (profiler captures it)
    detect_kernel<<<1, 256>>>(es);
    init_kernel<<<(NN * (HD2 / 4) + 255) / 256, 256>>>();
    w1split_kernel<<<(512 * 128 + 255) / 256, 256>>>(W1);
    gemm1_mma<<<(NN + 127) / 128, 256, G1_SMEM>>>(x);

    deg_kernel<<<(E + 255) / 256, 256>>>(es, E, dinv_s);
    deg_kernel<<<(Ek + 255) / 256, 256>>>(ek, Ek, dinv_k);
    dinv_kernel<<<(NN + 255) / 256, 256>>>();

    // column-phased scatter: cols [0,64) for both graphs, then cols [64,128)
    {
        int gS = (E * 16 + 255) / 256, gK = (Ek * 16 + 255) / 256;
        scatter64_kernel<<<gS, 256>>>(es, E, dinv_s, 0,  0);
        scatter64_kernel<<<gK, 256>>>(ek, Ek, dinv_k, HD, 0);
        scatter64_kernel<<<gS, 256>>>(es, E, dinv_s, 0,  64);
        scatter64_kernel<<<gK, 256>>>(ek, Ek, dinv_k, HD, 64);
    }

    gemm2_kernel<<<(NN + 127) / 128, 256>>>(W2, b1);
    {
        long long ts = (long long)E * 10;
        long long tk = (long long)Ek * 10;
        scatter40_kernel<<<(unsigned)((ts + 255) / 256), 256>>>(es, E, dinv_s, 0);
        scatter40_kernel<<<(unsigned)((tk + 255) / 256), 256>>>(ek, Ek, dinv_k, NC);
    }
    final_kernel<<<(NN + 7) / 8, 256>>>(b2, Wlin, blin, out);
}

// round 12
// speedup vs baseline: 1.1978x; 1.0810x over previous
#include <cuda_runtime.h>
#include <cuda_bf16.h>
#include <cuda_fp16.h>
#include <cstdint>
#include <math.h>

#define NN 100000
#define F_IN 500
#define HD 128
#define NC 40
#define HD2 256
#define NC2 80

__device__ float  g_h1[(size_t)NN * HD];     // x @ W1 (fp32, self-loop path)
__device__ __half g_h1h[(size_t)NN * HD];    // fp16 mirror for scatter gather
__device__ float  g_R1[(size_t)NN * HD2];    // layer-1 atomic accumulator
__device__ float  g_h2[(size_t)NN * NC];     // R1' @ W2 (fp32)
__device__ __half g_h2h[(size_t)NN * NC];    // fp16 mirror for scatter gather
__device__ float  g_R2[(size_t)NN * NC2];    // layer-2 atomic accumulator
__device__ float  g_dinv_s[NN];
__device__ float  g_dinv_k[NN];
__device__ int    g_is64;
// W1^T split into bf16 hi/lo, layout [chunk=8][n=128][k=64]
__device__ __nv_bfloat16 g_W1h[8 * 128 * 64];
__device__ __nv_bfloat16 g_W1l[8 * 128 * 64];
// W2^T split into bf16 hi/lo, layout [chunk=4][n=64][k=64] (n padded 40->64)
__device__ __nv_bfloat16 g_W2h[4 * 64 * 64];
__device__ __nv_bfloat16 g_W2l[4 * 64 * 64];

// ---------------- dtype detection (int32 vs int64 edge indices) -------------
__global__ void detect_kernel(const void* edges) {
    __shared__ int bad;
    if (threadIdx.x == 0) bad = 0;
    __syncthreads();
    const long long* p = (const long long*)edges;
    for (int i = threadIdx.x; i < 2048; i += blockDim.x) {
        long long v = p[i];
        if (v < 0 || v >= NN) bad = 1;
    }
    __syncthreads();
    if (threadIdx.x == 0) g_is64 = bad ? 0 : 1;
}

__device__ __forceinline__ int edge_at(const void* edges, long long idx, bool is64) {
    return is64 ? (int)((const long long*)edges)[idx] : ((const int*)edges)[idx];
}

// ---------------- init accumulators + degree seeds --------------------------
__global__ void init_kernel() {
    int i = blockIdx.x * blockDim.x + threadIdx.x;
    float4 z = make_float4(0.f, 0.f, 0.f, 0.f);
    float4 one = make_float4(1.f, 1.f, 1.f, 1.f);
    if (i < NN * (HD2 / 4)) ((float4*)g_R1)[i] = z;
    if (i < NN * (NC2 / 4)) ((float4*)g_R2)[i] = z;
    if (i < NN / 4) { ((float4*)g_dinv_s)[i] = one; ((float4*)g_dinv_k)[i] = one; }
}

__global__ void deg_kernel(const void* edges, int E, float* deg) {
    int e = blockIdx.x * blockDim.x + threadIdx.x;
    if (e >= E) return;
    bool is64 = g_is64;
    int dst = edge_at(edges, (long long)E + e, is64);
    atomicAdd(&deg[dst], 1.0f);
}

__global__ void dinv_kernel() {
    int i = blockIdx.x * blockDim.x + threadIdx.x;
    if (i < NN) {
        g_dinv_s[i] = rsqrtf(g_dinv_s[i]);
        g_dinv_k[i] = rsqrtf(g_dinv_k[i]);
    }
}

// ---------------- weight split kernels --------------------------------------
__global__ void w1split_kernel(const float* __restrict__ W1) {
    int i = blockIdx.x * blockDim.x + threadIdx.x;
    if (i >= 512 * 128) return;
    int k = i >> 7, n = i & 127;
    float v = (k < F_IN) ? W1[(size_t)k * HD + n] : 0.f;
    __nv_bfloat16 h = __float2bfloat16_rn(v);
    __nv_bfloat16 l = __float2bfloat16_rn(v - __bfloat162float(h));
    int chunk = k >> 6, kk = k & 63;
    int off = (chunk * 128 + n) * 64 + kk;
    g_W1h[off] = h;
    g_W1l[off] = l;
}

__global__ void w2split_kernel(const float* __restrict__ W2) {
    int i = blockIdx.x * blockDim.x + threadIdx.x;
    if (i >= 256 * 64) return;
    int k = i >> 6, n = i & 63;
    float v = (n < NC) ? W2[(size_t)k * NC + n] : 0.f;
    __nv_bfloat16 h = __float2bfloat16_rn(v);
    __nv_bfloat16 l = __float2bfloat16_rn(v - __bfloat162float(h));
    int chunk = k >> 6, kk = k & 63;
    int off = (chunk * 64 + n) * 64 + kk;
    g_W2h[off] = h;
    g_W2l[off] = l;
}

// ---------------- shared helpers --------------------------------------------
__device__ __forceinline__ void mma16816(float* c, const uint32_t* a, const uint32_t* b) {
    asm volatile("mma.sync.aligned.m16n8k16.row.col.f32.bf16.bf16.f32 "
                 "{%0,%1,%2,%3}, {%4,%5,%6,%7}, {%8,%9}, {%0,%1,%2,%3};"
                 : "+f"(c[0]), "+f"(c[1]), "+f"(c[2]), "+f"(c[3])
                 : "r"(a[0]), "r"(a[1]), "r"(a[2]), "r"(a[3]), "r"(b[0]), "r"(b[1]));
}

__device__ __forceinline__ uint32_t smem_u32(const void* p) {
    uint32_t a;
    asm("{ .reg .u64 t; cvta.to.shared.u64 t, %1; cvt.u32.u64 %0, t; }" : "=r"(a) : "l"(p));
    return a;
}

#define LDSM4(r0, r1, r2, r3, addr) \
    asm volatile("ldmatrix.sync.aligned.m8n8.x4.shared.b16 {%0,%1,%2,%3}, [%4];" \
                 : "=r"(r0), "=r"(r1), "=r"(r2), "=r"(r3) : "r"(addr))

#define LDA 72   // padded row length (bf16): 144B stride, conflict-free ldmatrix

// ---------------- GEMM1: HMMA + ldmatrix, 2 CTAs/SM -------------------------
#define G1_SMEM (4 * 128 * LDA * 2)

__global__ void __launch_bounds__(256, 2) gemm1_mma(const float* __restrict__ x) {
    extern __shared__ __nv_bfloat16 smem[];
    __nv_bfloat16* Ah = smem;                 // [128][LDA]
    __nv_bfloat16* Al = Ah + 128 * LDA;
    __nv_bfloat16* Bh = Al + 128 * LDA;       // [128 n][LDA]
    __nv_bfloat16* Bl = Bh + 128 * LDA;

    int tid = threadIdx.x;
    int lane = tid & 31, wid = tid >> 5;
    int wm = wid & 3, wn = wid >> 2;          // rows wm*32, cols wn*64
    int gr = lane >> 2, tig = lane & 3;
    int row0 = blockIdx.x * 128;

    int ar = tid >> 1;
    int akh = (tid & 1) * 32;
    bool rowok = (row0 + ar) < NN;
    const float* xp = x + (size_t)(row0 + ar) * F_IN;

    // ldmatrix per-lane byte offsets (row-part; add kk*2 per k-step)
    uint32_t uAh = smem_u32(Ah), uAl = smem_u32(Al);
    uint32_t uBh = smem_u32(Bh), uBl = smem_u32(Bl);
    uint32_t aoff = (uint32_t)(((wm * 32 + (lane & 15)) * LDA + (lane >> 4) * 8) * 2);
    int brow = ((lane >> 4) & 1) * 8 + (lane & 7);
    int bk   = ((lane >> 3) & 1) * 8;
    uint32_t boff[4];
#pragma unroll
    for (int g = 0; g < 4; g++)
        boff[g] = (uint32_t)(((wn * 64 + g * 16 + brow) * LDA + bk) * 2);

    float c[2][8][4];
#pragma unroll
    for (int mt = 0; mt < 2; mt++)
#pragma unroll
        for (int nt = 0; nt < 8; nt++)
#pragma unroll
            for (int q = 0; q < 4; q++) c[mt][nt][q] = 0.f;

    for (int chunk = 0; chunk < 8; chunk++) {
        int k0 = chunk * 64;
        // ---- load A: fp32 -> split bf16 hi/lo into smem ----
#pragma unroll
        for (int j = 0; j < 32; j += 8) {
            int kk = akh + j, gk = k0 + kk;
            float4 a = make_float4(0.f, 0.f, 0.f, 0.f);
            float4 b = make_float4(0.f, 0.f, 0.f, 0.f);
            if (rowok && gk < F_IN)     a = *(const float4*)(xp + gk);
            if (rowok && gk + 4 < F_IN) b = *(const float4*)(xp + gk + 4);
            float v[8] = {a.x, a.y, a.z, a.w, b.x, b.y, b.z, b.w};
            __nv_bfloat16 hb[8], lb[8];
#pragma unroll
            for (int q = 0; q < 8; q++) {
                hb[q] = __float2bfloat16_rn(v[q]);
                lb[q] = __float2bfloat16_rn(v[q] - __bfloat162float(hb[q]));
            }
            *(uint4*)&Ah[ar * LDA + kk] = *(uint4*)hb;
            *(uint4*)&Al[ar * LDA + kk] = *(uint4*)lb;
        }
        // ---- load B: copy pre-split W1^T [n][k64] ----
        {
            const uint4* sh = (const uint4*)(g_W1h + chunk * 128 * 64);
            const uint4* sl = (const uint4*)(g_W1l + chunk * 128 * 64);
#pragma unroll
            for (int it = 0; it < 4; it++) {
                int idx = tid + it * 256;
                int n = idx >> 3, kg = idx & 7;
                *(uint4*)&Bh[n * LDA + kg * 8] = sh[idx];
                *(uint4*)&Bl[n * LDA + kg * 8] = sl[idx];
            }
        }
        __syncthreads();
#pragma unroll
        for (int ks = 0; ks < 4; ks++) {
            uint32_t kb = (uint32_t)(ks * 16 * 2);
            uint32_t ah[2][4], al[2][4], bhf[8][2], blf[8][2];
#pragma unroll
            for (int mt = 0; mt < 2; mt++) {
                uint32_t mo = aoff + (uint32_t)(mt * 16 * LDA * 2) + kb;
                LDSM4(ah[mt][0], ah[mt][1], ah[mt][2], ah[mt][3], uAh + mo);
                LDSM4(al[mt][0], al[mt][1], al[mt][2], al[mt][3], uAl + mo);
            }
#pragma unroll
            for (int g = 0; g < 4; g++) {
                LDSM4(bhf[2 * g][0], bhf[2 * g][1], bhf[2 * g + 1][0], bhf[2 * g + 1][1],
                      uBh + boff[g] + kb);
                LDSM4(blf[2 * g][0], blf[2 * g][1], blf[2 * g + 1][0], blf[2 * g + 1][1],
                      uBl + boff[g] + kb);
            }
#pragma unroll
            for (int mt = 0; mt < 2; mt++)
#pragma unroll
                for (int nt = 0; nt < 8; nt++) {
                    mma16816(c[mt][nt], ah[mt], bhf[nt]);
                    mma16816(c[mt][nt], al[mt], bhf[nt]);
                    mma16816(c[mt][nt], ah[mt], blf[nt]);
                }
        }
        __syncthreads();
    }
    // ---- epilogue: fp32 + fp16 mirror ----
#pragma unroll
    for (int mt = 0; mt < 2; mt++) {
        int r0 = row0 + wm * 32 + mt * 16 + gr;
#pragma unroll
        for (int nt = 0; nt < 8; nt++) {
            int cc = wn * 64 + nt * 8 + tig * 2;
            if (r0 < NN) {
                *(float2*)(g_h1 + (size_t)r0 * HD + cc) = make_float2(c[mt][nt][0], c[mt][nt][1]);
                *(__half2*)(g_h1h + (size_t)r0 * HD + cc) = __floats2half2_rn(c[mt][nt][0], c[mt][nt][1]);
            }
            if (r0 + 8 < NN) {
                *(float2*)(g_h1 + (size_t)(r0 + 8) * HD + cc) = make_float2(c[mt][nt][2], c[mt][nt][3]);
                *(__half2*)(g_h1h + (size_t)(r0 + 8) * HD + cc) = __floats2half2_rn(c[mt][nt][2], c[mt][nt][3]);
            }
        }
    }
}

// -------- scatter 64 cols per pass, fp16 gather: 2 edges/warp, 16 lanes -----
__global__ void scatter64_kernel(const void* edges, int E,
                                 const float* __restrict__ dinv,
                                 int base, int colbase) {
    int t = blockIdx.x * blockDim.x + threadIdx.x;
    int e = t >> 4;
    int l16 = t & 15;
    if (e >= E) return;
    bool is64 = g_is64;
    int src = edge_at(edges, e, is64);
    int dst = edge_at(edges, (long long)E + e, is64);
    float s = __ldg(&dinv[src]);
    const __half2* hp = (const __half2*)(g_h1h + (size_t)src * HD + colbase + l16 * 4);
    float2 f0 = __half22float2(hp[0]);
    float2 f1 = __half22float2(hp[1]);
    float* p = g_R1 + (size_t)dst * HD2 + base + colbase + l16 * 4;
    asm volatile("red.global.add.v4.f32 [%0], {%1,%2,%3,%4};"
                 :: "l"(p), "f"(f0.x * s), "f"(f0.y * s), "f"(f1.x * s), "f"(f1.y * s)
                 : "memory");
}

// ---------------- GEMM2: HMMA + ldmatrix, finalize1 fused on A-load ---------
#define G2_SMEM ((2 * 128 * LDA + 2 * 64 * LDA) * 2)

__global__ void __launch_bounds__(256, 2) gemm2_mma(const float* __restrict__ b1) {
    extern __shared__ __nv_bfloat16 smem[];
    __nv_bfloat16* Ah = smem;                 // [128][LDA]
    __nv_bfloat16* Al = Ah + 128 * LDA;
    __nv_bfloat16* Bh = Al + 128 * LDA;       // [64 n][LDA]
    __nv_bfloat16* Bl = Bh + 64 * LDA;
    __shared__ float sb1[HD];

    int tid = threadIdx.x;
    int lane = tid & 31, wid = tid >> 5;
    int wm = wid & 3, wn = wid >> 2;          // rows wm*32, cols wn*32
    int gr = lane >> 2, tig = lane & 3;
    int row0 = blockIdx.x * 128;

    int ar = tid >> 1;
    int akh = (tid & 1) * 32;
    int grow = row0 + ar;
    bool rowok = grow < NN;
    float dsv = 0.f, dkv = 0.f;
    if (rowok) { dsv = g_dinv_s[grow]; dkv = g_dinv_k[grow]; }
    if (tid < HD) sb1[tid] = b1[tid];
    __syncthreads();

    uint32_t uAh = smem_u32(Ah), uAl = smem_u32(Al);
    uint32_t uBh = smem_u32(Bh), uBl = smem_u32(Bl);
    uint32_t aoff = (uint32_t)(((wm * 32 + (lane & 15)) * LDA + (lane >> 4) * 8) * 2);
    int brow = ((lane >> 4) & 1) * 8 + (lane & 7);
    int bk   = ((lane >> 3) & 1) * 8;
    uint32_t boff[2];
#pragma unroll
    for (int g = 0; g < 2; g++)
        boff[g] = (uint32_t)(((wn * 32 + g * 16 + brow) * LDA + bk) * 2);

    float c[2][4][4];
#pragma unroll
    for (int mt = 0; mt < 2; mt++)
#pragma unroll
        for (int nt = 0; nt < 4; nt++)
#pragma unroll
            for (int q = 0; q < 4; q++) c[mt][nt][q] = 0.f;

    for (int chunk = 0; chunk < 4; chunk++) {
        int k0 = chunk * 64;
        float dv = (k0 >= HD) ? dkv : dsv;
        float dv2 = dv * dv;
        // ---- load A: finalize1 (norm+self+bias+relu) then split bf16 -------
#pragma unroll
        for (int j = 0; j < 32; j += 8) {
            int kk = akh + j;
            int cg = k0 + kk;                 // global col 0..255
            int cm = cg & (HD - 1);
            float v[8];
#pragma unroll
            for (int q = 0; q < 8; q += 4) {
                float4 r = make_float4(0.f, 0.f, 0.f, 0.f);
                float4 h = make_float4(0.f, 0.f, 0.f, 0.f);
                if (rowok) {
                    r = *(const float4*)(g_R1 + (size_t)grow * HD2 + cg + q);
                    h = *(const float4*)(g_h1 + (size_t)grow * HD + cm + q);
                }
                float4 bb = *(const float4*)&sb1[cm + q];
                v[q + 0] = fmaxf(fmaf(r.x, dv, fmaf(h.x, dv2, bb.x)), 0.f);
                v[q + 1] = fmaxf(fmaf(r.y, dv, fmaf(h.y, dv2, bb.y)), 0.f);
                v[q + 2] = fmaxf(fmaf(r.z, dv, fmaf(h.z, dv2, bb.z)), 0.f);
                v[q + 3] = fmaxf(fmaf(r.w, dv, fmaf(h.w, dv2, bb.w)), 0.f);
            }
            __nv_bfloat16 hb[8], lb[8];
#pragma unroll
            for (int q = 0; q < 8; q++) {
                hb[q] = __float2bfloat16_rn(v[q]);
                lb[q] = __float2bfloat16_rn(v[q] - __bfloat162float(hb[q]));
            }
            *(uint4*)&Ah[ar * LDA + kk] = *(uint4*)hb;
            *(uint4*)&Al[ar * LDA + kk] = *(uint4*)lb;
        }
        // ---- load B: copy pre-split W2^T [n=64][k64] ----
        {
            const uint4* sh = (const uint4*)(g_W2h + chunk * 64 * 64);
            const uint4* sl = (const uint4*)(g_W2l + chunk * 64 * 64);
#pragma unroll
            for (int it = 0; it < 2; it++) {
                int idx = tid + it * 256;
                int n = idx >> 3, kg = idx & 7;
                *(uint4*)&Bh[n * LDA + kg * 8] = sh[idx];
                *(uint4*)&Bl[n * LDA + kg * 8] = sl[idx];
            }
        }
        __syncthreads();
#pragma unroll
        for (int ks = 0; ks < 4; ks++) {
            uint32_t kb = (uint32_t)(ks * 16 * 2);
            uint32_t ah[2][4], al[2][4], bhf[4][2], blf[4][2];
#pragma unroll
            for (int mt = 0; mt < 2; mt++) {
                uint32_t mo = aoff + (uint32_t)(mt * 16 * LDA * 2) + kb;
                LDSM4(ah[mt][0], ah[mt][1], ah[mt][2], ah[mt][3], uAh + mo);
                LDSM4(al[mt][0], al[mt][1], al[mt][2], al[mt][3], uAl + mo);
            }
#pragma unroll
            for (int g = 0; g < 2; g++) {
                LDSM4(bhf[2 * g][0], bhf[2 * g][1], bhf[2 * g + 1][0], bhf[2 * g + 1][1],
                      uBh + boff[g] + kb);
                LDSM4(blf[2 * g][0], blf[2 * g][1], blf[2 * g + 1][0], blf[2 * g + 1][1],
                      uBl + boff[g] + kb);
            }
#pragma unroll
            for (int mt = 0; mt < 2; mt++)
#pragma unroll
                for (int nt = 0; nt < 4; nt++) {
                    mma16816(c[mt][nt], ah[mt], bhf[nt]);
                    mma16816(c[mt][nt], al[mt], bhf[nt]);
                    mma16816(c[mt][nt], ah[mt], blf[nt]);
                }
        }
        __syncthreads();
    }
    // ---- epilogue: cols < 40 only, fp32 + fp16 mirror ----
#pragma unroll
    for (int mt = 0; mt < 2; mt++) {
        int r0 = row0 + wm * 32 + mt * 16 + gr;
#pragma unroll
        for (int nt = 0; nt < 4; nt++) {
            int cc = wn * 32 + nt * 8 + tig * 2;
            if (cc < NC) {
                if (r0 < NN) {
                    *(float2*)(g_h2 + (size_t)r0 * NC + cc) = make_float2(c[mt][nt][0], c[mt][nt][1]);
                    *(__half2*)(g_h2h + (size_t)r0 * NC + cc) = __floats2half2_rn(c[mt][nt][0], c[mt][nt][1]);
                }
                if (r0 + 8 < NN) {
                    *(float2*)(g_h2 + (size_t)(r0 + 8) * NC + cc) = make_float2(c[mt][nt][2], c[mt][nt][3]);
                    *(__half2*)(g_h2h + (size_t)(r0 + 8) * NC + cc) = __floats2half2_rn(c[mt][nt][2], c[mt][nt][3]);
                }
            }
        }
    }
}

// ---------------- scatter 40-wide fp16 gather: 10 threads per edge ----------
__global__ void scatter40_kernel(const void* edges, int E,
                                 const float* __restrict__ dinv, int base) {
    long long t = (long long)blockIdx.x * blockDim.x + threadIdx.x;
    if (t >= (long long)E * 10) return;
    int e = (int)(t / 10), j = (int)(t % 10);
    bool is64 = g_is64;
    int src = edge_at(edges, e, is64);
    int dst = edge_at(edges, (long long)E + e, is64);
    float s = __ldg(&dinv[src]);
    const __half2* hp = (const __half2*)(g_h2h + (size_t)src * NC + j * 4);
    float2 f0 = __half22float2(hp[0]);
    float2 f1 = __half22float2(hp[1]);
    float* p = g_R2 + (size_t)dst * NC2 + base + j * 4;
    asm volatile("red.global.add.v4.f32 [%0], {%1,%2,%3,%4};"
                 :: "l"(p), "f"(f0.x * s), "f"(f0.y * s), "f"(f1.x * s), "f"(f1.y * s)
                 : "memory");
}

// ---------------- final: finalize L2 + Wlin + log_softmax -------------------
__global__ void __launch_bounds__(256) final_kernel(const float* __restrict__ b2,
                                                    const float* __restrict__ Wlin,
                                                    const float* __restrict__ blin,
                                                    float* __restrict__ out) {
    __shared__ float sWT[NC2 * NC];   // sWT[j*NC + c] = Wlin[c*NC2 + j]
    __shared__ float sb2[NC], sblin[NC];
    __shared__ float sr2[8][NC2];
    int tid = threadIdx.x;
    for (int i = tid; i < NC * NC2; i += 256) {
        int cidx = i / NC2, j = i % NC2;
        sWT[j * NC + cidx] = Wlin[i];
    }
    if (tid < NC) { sb2[tid] = b2[tid]; sblin[tid] = blin[tid]; }
    __syncthreads();
    int warp = tid >> 5, lane = tid & 31;
    int node = blockIdx.x * 8 + warp;
    if (node >= NN) return;

    float ds = g_dinv_s[node], dk = g_dinv_k[node];
    float ds2 = ds * ds, dk2 = dk * dk;
    for (int j = lane; j < NC; j += 32) {
        float h = g_h2[(size_t)node * NC + j];
        sr2[warp][j]      = fmaf(g_R2[(size_t)node * NC2 + j],      ds, fmaf(h, ds2, sb2[j]));
        sr2[warp][NC + j] = fmaf(g_R2[(size_t)node * NC2 + NC + j], dk, fmaf(h, dk2, sb2[j]));
    }
    __syncwarp();

    float l1, l2 = -INFINITY;
    {
        float a = sblin[lane];
#pragma unroll 8
        for (int j = 0; j < NC2; j++) a = fmaf(sr2[warp][j], sWT[j * NC + lane], a);
        l1 = a;
    }
    if (lane < 8) {
        int cidx = 32 + lane;
        float a = sblin[cidx];
#pragma unroll 8
        for (int j = 0; j < NC2; j++) a = fmaf(sr2[warp][j], sWT[j * NC + cidx], a);
        l2 = a;
    }
    float m = fmaxf(l1, l2);
#pragma unroll
    for (int off = 16; off > 0; off >>= 1)
        m = fmaxf(m, __shfl_xor_sync(0xffffffffu, m, off));
    float s = expf(l1 - m) + ((lane < 8) ? expf(l2 - m) : 0.f);
#pragma unroll
    for (int off = 16; off > 0; off >>= 1)
        s += __shfl_xor_sync(0xffffffffu, s, off);
    float lse = logf(s);
    out[(size_t)node * NC + lane] = l1 - m - lse;
    if (lane < 8) out[(size_t)node * NC + 32 + lane] = l2 - m - lse;
}

// ---------------------------------------------------------------------------
extern "C" void kernel_launch(void* const* d_in, const int* in_sizes, int n_in,
                              void* d_out, int out_size) {
    const float* x    = (const float*)d_in[0];
    const void*  es   = d_in[1];
    const void*  ek   = d_in[2];
    const float* W1   = (const float*)d_in[3];
    const float* b1   = (const float*)d_in[4];
    const float* W2   = (const float*)d_in[5];
    const float* b2   = (const float*)d_in[6];
    const float* Wlin = (const float*)d_in[7];
    const float* blin = (const float*)d_in[8];
    float* out = (float*)d_out;

    int E  = in_sizes[1] / 2;
    int Ek = in_sizes[2] / 2;

    float *dinv_s, *dinv_k;
    cudaGetSymbolAddress((void**)&dinv_s, g_dinv_s);
    cudaGetSymbolAddress((void**)&dinv_k, g_dinv_k);

    static int smem_set = 0;
    if (!smem_set) {
        cudaFuncSetAttribute(gemm1_mma, cudaFuncAttributeMaxDynamicSharedMemorySize, G1_SMEM);
        cudaFuncSetAttribute(gemm2_mma, cudaFuncAttributeMaxDynamicSharedMemorySize, G2_SMEM);
        smem_set = 1;
    }

    // launch #4 = gemm1_mma (profiler captures it)
    detect_kernel<<<1, 256>>>(es);
    init_kernel<<<(NN * (HD2 / 4) + 255) / 256, 256>>>();
    w1split_kernel<<<(512 * 128 + 255) / 256, 256>>>(W1);
    gemm1_mma<<<(NN + 127) / 128, 256, G1_SMEM>>>(x);

    w2split_kernel<<<(256 * 64 + 255) / 256, 256>>>(W2);
    deg_kernel<<<(E + 255) / 256, 256>>>(es, E, dinv_s);
    deg_kernel<<<(Ek + 255) / 256, 256>>>(ek, Ek, dinv_k);
    dinv_kernel<<<(NN + 255) / 256, 256>>>();

    // column-phased scatter: cols [0,64) for both graphs, then cols [64,128)
    {
        int gS = (E * 16 + 255) / 256, gK = (Ek * 16 + 255) / 256;
        scatter64_kernel<<<gS, 256>>>(es, E, dinv_s, 0,  0);
        scatter64_kernel<<<gK, 256>>>(ek, Ek, dinv_k, HD, 0);
        scatter64_kernel<<<gS, 256>>>(es, E, dinv_s, 0,  64);
        scatter64_kernel<<<gK, 256>>>(ek, Ek, dinv_k, HD, 64);
    }

    gemm2_mma<<<(NN + 127) / 128, 256, G2_SMEM>>>(b1);
    {
        long long ts = (long long)E * 10;
        long long tk = (long long)Ek * 10;
        scatter40_kernel<<<(unsigned)((ts + 255) / 256), 256>>>(es, E, dinv_s, 0);
        scatter40_kernel<<<(unsigned)((tk + 255) / 256), 256>>>(ek, Ek, dinv_k, NC);
    }
    final_kernel<<<(NN + 7) / 8, 256>>>(b2, Wlin, blin, out);
}